// round 13
// baseline (speedup 1.0000x reference)
#include <cuda_runtime.h>
#include <math_constants.h>

#define N_NODES   50000
#define N_EDGES   800000
#define F_IN      300
#define HEADS     4
#define PER_HEAD  32
#define HIDDEN    128
#define N_CLASSES 9
#define NEG_SLOPE 0.2f

#define SCAN_BLOCKS 196   // ceil(50000/256)

// ---------------- scratch (static device globals; no allocation) ----------------
__device__ __align__(16) float g_bufA[N_NODES * HIDDEN];
__device__ __align__(16) float g_bufB[N_NODES * HIDDEN];
__device__ __align__(16) float g_feat3[N_NODES * N_CLASSES];
__device__ __align__(16) float g_asrc[N_NODES * HEADS];
__device__ __align__(16) float g_adst[N_NODES * HEADS];
__device__ float g_asrc3[N_NODES];
__device__ float g_adst3[N_NODES];
__device__ int   g_deg[N_NODES];
__device__ int   g_cur[N_NODES];
__device__ int   g_off[N_NODES + 1];
__device__ int   g_csr[N_EDGES];
__device__ int   g_bsum[SCAN_BLOCKS];
__device__ int   g_is64;

// ---------------- init: zero counters + parallel dtype detection ----------------
__global__ void k_init(const void* ei) {
    int i = blockIdx.x * blockDim.x + threadIdx.x;
    if (i < N_NODES) { g_deg[i] = 0; g_cur[i] = 0; }
    if (blockIdx.x == 0) {
        int ok = 1;
        if (threadIdx.x < 64) {
            long long v = ((const long long*)ei)[threadIdx.x];
            ok = (v >= 0 && v < N_NODES) ? 1 : 0;
        }
        int all = __syncthreads_and(ok);
        if (threadIdx.x == 0) g_is64 = all;
    }
}

__device__ __forceinline__ int edge_at(const void* ei, int idx) {
    if (g_is64) return (int)((const long long*)ei)[idx];
    return ((const int*)ei)[idx];
}

// ---------------- CSR construction ----------------
__global__ void k_hist(const void* __restrict__ ei) {
    int e = blockIdx.x * blockDim.x + threadIdx.x;
    if (e < N_EDGES) {
        int d = edge_at(ei, N_EDGES + e);
        atomicAdd(&g_deg[d], 1);
    }
}

__global__ void k_bsum() {
    __shared__ int s[256];
    int tid = threadIdx.x;
    int i = blockIdx.x * 256 + tid;
    s[tid] = (i < N_NODES) ? g_deg[i] : 0;
    __syncthreads();
    for (int st = 128; st; st >>= 1) {
        if (tid < st) s[tid] += s[tid + st];
        __syncthreads();
    }
    if (tid == 0) g_bsum[blockIdx.x] = s[0];
}

// local scan + redundant scan of block sums (folds old k_bscan in)
__global__ void k_lscan() {
    __shared__ int s[256];
    __shared__ int bp[256];
    int tid = threadIdx.x;

    int bv = (tid < SCAN_BLOCKS) ? g_bsum[tid] : 0;
    bp[tid] = bv;
    __syncthreads();
    for (int off = 1; off < 256; off <<= 1) {
        int t = (tid >= off) ? bp[tid - off] : 0;
        __syncthreads();
        bp[tid] += t;
        __syncthreads();
    }
    int myoff = (blockIdx.x > 0) ? bp[blockIdx.x - 1] : 0;

    int i = blockIdx.x * 256 + tid;
    int v = (i < N_NODES) ? g_deg[i] : 0;
    s[tid] = v;
    __syncthreads();
    for (int off = 1; off < 256; off <<= 1) {
        int t = (tid >= off) ? s[tid - off] : 0;
        __syncthreads();
        s[tid] += t;
        __syncthreads();
    }
    if (i < N_NODES) g_off[i] = (s[tid] - v) + myoff;
    if (blockIdx.x == 0 && tid == 0) g_off[N_NODES] = N_EDGES;
}

__global__ void k_scatter(const void* __restrict__ ei) {
    int e = blockIdx.x * blockDim.x + threadIdx.x;
    if (e < N_EDGES) {
        int src = edge_at(ei, e);
        int dst = edge_at(ei, N_EDGES + e);
        int p = g_off[dst] + atomicAdd(&g_cur[dst], 1);
        g_csr[p] = src;
    }
}

// ---------------- TF32 helpers ----------------
__device__ __forceinline__ unsigned f2tf32(float x) {
    unsigned r;
    asm("cvt.rna.tf32.f32 %0, %1;" : "=r"(r) : "f"(x));
    return r;
}
__device__ __forceinline__ void split_tf32(float x, unsigned& hi, unsigned& lo) {
    hi = f2tf32(x);
    lo = f2tf32(x - __uint_as_float(hi));
}
__device__ __forceinline__ void mma_tf32(float* c, const unsigned* a, unsigned b0, unsigned b1) {
    asm volatile(
        "mma.sync.aligned.m16n8k8.row.col.f32.tf32.tf32.f32 "
        "{%0,%1,%2,%3}, {%4,%5,%6,%7}, {%8,%9}, {%0,%1,%2,%3};\n"
        : "+f"(c[0]), "+f"(c[1]), "+f"(c[2]), "+f"(c[3])
        : "r"(a[0]), "r"(a[1]), "r"(a[2]), "r"(a[3]), "r"(b0), "r"(b1));
}

// ---------------- Tensor-core GEMM (single-buffered) + fused attention epilogue ----------------
// C[M,128] = A[M,K] @ B[K,128]; 2-term TF32 (ah*bh + al*bh).
// Block 128x128, BK=16, 8 warps. (Round-10 proven config.)
#define GSTRIDE 136
__global__ void __launch_bounds__(256, 2) k_gemm_tc(const float* __restrict__ A,
                                                    const float* __restrict__ B,
                                                    float* __restrict__ C,
                                                    const float* __restrict__ as,
                                                    const float* __restrict__ ad,
                                                    float* __restrict__ asrc,
                                                    float* __restrict__ adst,
                                                    int M, int K) {
    __shared__ float As[16 * GSTRIDE];
    __shared__ float Bh[16 * GSTRIDE];
    const unsigned* Bh_u = (const unsigned*)Bh;

    int tid = threadIdx.x;
    int wid = tid >> 5, lane = tid & 31;
    int l4 = lane & 3, lg = lane >> 2;
    int wm = (wid >> 1) * 32;
    int wn = (wid & 1) * 64;
    int mbase = blockIdx.x * 128;

    float c[2][8][4];
#pragma unroll
    for (int mt = 0; mt < 2; mt++)
#pragma unroll
        for (int nt = 0; nt < 8; nt++)
#pragma unroll
            for (int e = 0; e < 4; e++) c[mt][nt][e] = 0.f;

    for (int kt = 0; kt < K; kt += 16) {
        __syncthreads();
#pragma unroll
        for (int i = 0; i < 2; i++) {
            int a_id = tid + i * 256;
            int row = a_id >> 2;
            int kq = (a_id & 3) * 4;
            int gr = mbase + row, gc = kt + kq;
            float4 av = make_float4(0.f, 0.f, 0.f, 0.f);
            if (gr < M && gc < K)
                av = *(const float4*)(A + (size_t)gr * K + gc);
            As[(kq + 0) * GSTRIDE + row] = av.x;
            As[(kq + 1) * GSTRIDE + row] = av.y;
            As[(kq + 2) * GSTRIDE + row] = av.z;
            As[(kq + 3) * GSTRIDE + row] = av.w;
        }
#pragma unroll
        for (int i = 0; i < 2; i++) {
            int b_id = tid + i * 256;
            int krow = b_id >> 5;
            int col4 = (b_id & 31) * 4;
            int gk = kt + krow;
            float4 bv = make_float4(0.f, 0.f, 0.f, 0.f);
            if (gk < K)
                bv = *(const float4*)(B + (size_t)gk * HIDDEN + col4);
            float4 hv = make_float4(__uint_as_float(f2tf32(bv.x)),
                                    __uint_as_float(f2tf32(bv.y)),
                                    __uint_as_float(f2tf32(bv.z)),
                                    __uint_as_float(f2tf32(bv.w)));
            *(float4*)&Bh[krow * GSTRIDE + col4] = hv;
        }
        __syncthreads();

#pragma unroll
        for (int ks = 0; ks < 16; ks += 8) {
            unsigned ah[2][4], al[2][4];
#pragma unroll
            for (int mt = 0; mt < 2; mt++) {
#pragma unroll
                for (int e = 0; e < 4; e++) {
                    int kk = ks + l4 + ((e >> 1) * 4);
                    int mm = wm + mt * 16 + lg + ((e & 1) * 8);
                    float v = As[kk * GSTRIDE + mm];
                    split_tf32(v, ah[mt][e], al[mt][e]);
                }
            }
#pragma unroll
            for (int nt = 0; nt < 8; nt++) {
                int nn = wn + nt * 8 + lg;
                unsigned bh0 = Bh_u[(ks + l4) * GSTRIDE + nn];
                unsigned bh1 = Bh_u[(ks + l4 + 4) * GSTRIDE + nn];
#pragma unroll
                for (int mt = 0; mt < 2; mt++) {
                    mma_tf32(c[mt][nt], ah[mt], bh0, bh1);
                    mma_tf32(c[mt][nt], al[mt], bh0, bh1);
                }
            }
        }
    }

    // ---- writeback C ----
#pragma unroll
    for (int mt = 0; mt < 2; mt++) {
        int r0 = mbase + wm + mt * 16 + lg;
#pragma unroll
        for (int nt = 0; nt < 8; nt++) {
            int col = wn + nt * 8 + 2 * l4;
            if (r0 < M)
                *(float2*)(C + (size_t)r0 * HIDDEN + col) =
                    make_float2(c[mt][nt][0], c[mt][nt][1]);
            if (r0 + 8 < M)
                *(float2*)(C + (size_t)(r0 + 8) * HIDDEN + col) =
                    make_float2(c[mt][nt][2], c[mt][nt][3]);
        }
    }

    // ---- fused attention epilogue: this warp owns heads hbase, hbase+1 ----
    int hbase = wn ? 2 : 0;
#pragma unroll
    for (int mt = 0; mt < 2; mt++) {
        float s0 = 0.f, s1 = 0.f, s8_0 = 0.f, s8_1 = 0.f;
        float t0 = 0.f, t1 = 0.f, t8_0 = 0.f, t8_1 = 0.f;
#pragma unroll
        for (int nt = 0; nt < 8; nt++) {
            int cb = wn + nt * 8 + 2 * l4;
            float a0 = as[cb], a1 = as[cb + 1];
            float d0 = ad[cb], d1 = ad[cb + 1];
            float pp = c[mt][nt][0] * a0 + c[mt][nt][1] * a1;
            float p8 = c[mt][nt][2] * a0 + c[mt][nt][3] * a1;
            float q  = c[mt][nt][0] * d0 + c[mt][nt][1] * d1;
            float q8 = c[mt][nt][2] * d0 + c[mt][nt][3] * d1;
            if (nt < 4) { s0 += pp; s8_0 += p8; t0 += q; t8_0 += q8; }
            else        { s1 += pp; s8_1 += p8; t1 += q; t8_1 += q8; }
        }
#pragma unroll
        for (int o = 1; o <= 2; o <<= 1) {
            s0 += __shfl_xor_sync(0xffffffffu, s0, o);
            s1 += __shfl_xor_sync(0xffffffffu, s1, o);
            s8_0 += __shfl_xor_sync(0xffffffffu, s8_0, o);
            s8_1 += __shfl_xor_sync(0xffffffffu, s8_1, o);
            t0 += __shfl_xor_sync(0xffffffffu, t0, o);
            t1 += __shfl_xor_sync(0xffffffffu, t1, o);
            t8_0 += __shfl_xor_sync(0xffffffffu, t8_0, o);
            t8_1 += __shfl_xor_sync(0xffffffffu, t8_1, o);
        }
        int r0 = mbase + wm + mt * 16 + lg;
        if (l4 == 0) {
            if (r0 < M) {
                asrc[r0 * 4 + hbase] = s0;     asrc[r0 * 4 + hbase + 1] = s1;
                adst[r0 * 4 + hbase] = t0;     adst[r0 * 4 + hbase + 1] = t1;
            }
            if (r0 + 8 < M) {
                asrc[(r0 + 8) * 4 + hbase] = s8_0; asrc[(r0 + 8) * 4 + hbase + 1] = s8_1;
                adst[(r0 + 8) * 4 + hbase] = t8_0; adst[(r0 + 8) * 4 + hbase + 1] = t8_1;
            }
        }
    }
}

// ---------------- fused softmax + aggregation, warp/dst ----------------
// fuse_l3 != 0: compute layer-3 features (o @ W3) + attention scalars directly
// (replaces k_l3feat and skips the bufB write).
__global__ void __launch_bounds__(256) k_aggr(const float* __restrict__ feat,
                       const float* __restrict__ asrc, const float* __restrict__ adst,
                       const float* __restrict__ bias, float* __restrict__ out,
                       const float* __restrict__ W3, const float* __restrict__ as3,
                       const float* __restrict__ ad3, int fuse_l3) {
    __shared__ float sw[8][32][4];
    __shared__ int   ss[8][32];
    int warp = threadIdx.x >> 5;
    int n = (blockIdx.x * blockDim.x + threadIdx.x) >> 5;
    int lane = threadIdx.x & 31;
    if (n >= N_NODES) return;
    int beg = g_off[n], end = g_off[n + 1];
    int h = lane >> 3;

    float4 ad4 = *(const float4*)(adst + (size_t)n * 4);

    float4 acc = make_float4(0.f, 0.f, 0.f, 0.f);
    float den = 0.f;

    for (int bse = beg; bse < end; bse += 32) {
        int i = bse + lane;
        int s = 0;
        float4 w4 = make_float4(0.f, 0.f, 0.f, 0.f);
        if (i < end) {
            s = g_csr[i];
            float4 a4 = *(const float4*)(asrc + (size_t)s * 4);
            float ex_, ey_, ez_, ew_;
            ex_ = a4.x + ad4.x; ex_ = (ex_ > 0.f) ? ex_ : NEG_SLOPE * ex_;
            ey_ = a4.y + ad4.y; ey_ = (ey_ > 0.f) ? ey_ : NEG_SLOPE * ey_;
            ez_ = a4.z + ad4.z; ez_ = (ez_ > 0.f) ? ez_ : NEG_SLOPE * ez_;
            ew_ = a4.w + ad4.w; ew_ = (ew_ > 0.f) ? ew_ : NEG_SLOPE * ew_;
            w4.x = __expf(fminf(ex_, 60.f));
            w4.y = __expf(fminf(ey_, 60.f));
            w4.z = __expf(fminf(ez_, 60.f));
            w4.w = __expf(fminf(ew_, 60.f));
        }
        ss[warp][lane] = s;
        *(float4*)&sw[warp][lane][0] = w4;
        __syncwarp();

        int cnt = min(32, end - bse);
        int j = 0;
        for (; j + 4 <= cnt; j += 4) {
            int s0 = ss[warp][j],     s1 = ss[warp][j + 1];
            int s2 = ss[warp][j + 2], s3 = ss[warp][j + 3];
            float w0 = sw[warp][j][h],     w1 = sw[warp][j + 1][h];
            float w2 = sw[warp][j + 2][h], w3 = sw[warp][j + 3][h];
            float4 v0 = *(const float4*)(feat + (size_t)s0 * HIDDEN + lane * 4);
            float4 v1 = *(const float4*)(feat + (size_t)s1 * HIDDEN + lane * 4);
            float4 v2 = *(const float4*)(feat + (size_t)s2 * HIDDEN + lane * 4);
            float4 v3 = *(const float4*)(feat + (size_t)s3 * HIDDEN + lane * 4);
            acc.x = fmaf(w0, v0.x, acc.x); acc.y = fmaf(w0, v0.y, acc.y);
            acc.z = fmaf(w0, v0.z, acc.z); acc.w = fmaf(w0, v0.w, acc.w);
            acc.x = fmaf(w1, v1.x, acc.x); acc.y = fmaf(w1, v1.y, acc.y);
            acc.z = fmaf(w1, v1.z, acc.z); acc.w = fmaf(w1, v1.w, acc.w);
            acc.x = fmaf(w2, v2.x, acc.x); acc.y = fmaf(w2, v2.y, acc.y);
            acc.z = fmaf(w2, v2.z, acc.z); acc.w = fmaf(w2, v2.w, acc.w);
            acc.x = fmaf(w3, v3.x, acc.x); acc.y = fmaf(w3, v3.y, acc.y);
            acc.z = fmaf(w3, v3.z, acc.z); acc.w = fmaf(w3, v3.w, acc.w);
            den += (w0 + w1) + (w2 + w3);
        }
        for (; j < cnt; j++) {
            int sj = ss[warp][j];
            float wj = sw[warp][j][h];
            float4 v = *(const float4*)(feat + (size_t)sj * HIDDEN + lane * 4);
            acc.x = fmaf(wj, v.x, acc.x); acc.y = fmaf(wj, v.y, acc.y);
            acc.z = fmaf(wj, v.z, acc.z); acc.w = fmaf(wj, v.w, acc.w);
            den += wj;
        }
        __syncwarp();
    }
    bool has = (end > beg);
    float inv = has ? (1.f / den) : 0.f;
    float4 bv = *(const float4*)(bias + lane * 4);
    float4 o;
    o.x = acc.x * inv + bv.x;
    o.y = acc.y * inv + bv.y;
    o.z = acc.z * inv + bv.z;
    o.w = acc.w * inv + bv.w;
    o.x = (o.x > 0.f) ? o.x : expm1f(o.x);
    o.y = (o.y > 0.f) ? o.y : expm1f(o.y);
    o.z = (o.z > 0.f) ? o.z : expm1f(o.z);
    o.w = (o.w > 0.f) ? o.w : expm1f(o.w);

    if (!fuse_l3) {
        *(float4*)(out + (size_t)n * HIDDEN + lane * 4) = o;
    } else {
        const float* w3r = W3 + (lane * 4) * N_CLASSES;
        float hc[N_CLASSES];
#pragma unroll
        for (int cc = 0; cc < N_CLASSES; cc++) {
            float pp = o.x * w3r[cc]
                     + o.y * w3r[N_CLASSES + cc]
                     + o.z * w3r[2 * N_CLASSES + cc]
                     + o.w * w3r[3 * N_CLASSES + cc];
#pragma unroll
            for (int off = 16; off; off >>= 1)
                pp += __shfl_xor_sync(0xffffffffu, pp, off);
            hc[cc] = pp;
        }
        if (lane == 0) {
            float s = 0.f, d = 0.f;
#pragma unroll
            for (int cc = 0; cc < N_CLASSES; cc++) {
                g_feat3[n * N_CLASSES + cc] = hc[cc];
                s = fmaf(hc[cc], as3[cc], s);
                d = fmaf(hc[cc], ad3[cc], d);
            }
            g_asrc3[n] = s;
            g_adst3[n] = d;
        }
    }
}

// ---------------- layer-3 aggregation (no max pass) + ELU + log_softmax ----------------
__global__ void k_aggr3(const float* __restrict__ b3, float* __restrict__ out) {
    int n = (blockIdx.x * blockDim.x + threadIdx.x) >> 5;
    int lane = threadIdx.x & 31;
    if (n >= N_NODES) return;
    int beg = g_off[n], end = g_off[n + 1];
    float adn = g_adst3[n];

    float acc = 0.f, den = 0.f;
    for (int bse = beg; bse < end; bse += 32) {
        int i = bse + lane;
        int s = 0;
        float wg = 0.f;
        if (i < end) {
            s = g_csr[i];
            float e = g_asrc3[s] + adn;
            e = (e > 0.f) ? e : NEG_SLOPE * e;
            wg = __expf(fminf(e, 60.f));
        }
        int cnt = min(32, end - bse);
        int j = 0;
        for (; j + 4 <= cnt; j += 4) {
            int s0 = __shfl_sync(0xffffffffu, s, j);
            int s1 = __shfl_sync(0xffffffffu, s, j + 1);
            int s2 = __shfl_sync(0xffffffffu, s, j + 2);
            int s3 = __shfl_sync(0xffffffffu, s, j + 3);
            float w0 = __shfl_sync(0xffffffffu, wg, j);
            float w1 = __shfl_sync(0xffffffffu, wg, j + 1);
            float w2 = __shfl_sync(0xffffffffu, wg, j + 2);
            float w3 = __shfl_sync(0xffffffffu, wg, j + 3);
            if (lane < N_CLASSES) {
                float f0 = g_feat3[s0 * N_CLASSES + lane];
                float f1 = g_feat3[s1 * N_CLASSES + lane];
                float f2 = g_feat3[s2 * N_CLASSES + lane];
                float f3 = g_feat3[s3 * N_CLASSES + lane];
                acc = fmaf(w0, f0, acc); acc = fmaf(w1, f1, acc);
                acc = fmaf(w2, f2, acc); acc = fmaf(w3, f3, acc);
            }
            den += (w0 + w1) + (w2 + w3);
        }
        for (; j < cnt; j++) {
            int sj = __shfl_sync(0xffffffffu, s, j);
            float wj = __shfl_sync(0xffffffffu, wg, j);
            if (lane < N_CLASSES)
                acc = fmaf(wj, g_feat3[sj * N_CLASSES + lane], acc);
            den += wj;
        }
    }
    float o = (end > beg) ? (acc / den) : 0.f;
    if (lane < N_CLASSES) {
        o += b3[lane];
        o = (o > 0.f) ? o : expm1f(o);
    }
    float mv = (lane < N_CLASSES) ? o : -CUDART_INF_F;
#pragma unroll
    for (int s = 16; s; s >>= 1) mv = fmaxf(mv, __shfl_xor_sync(0xffffffffu, mv, s));
    float ex = (lane < N_CLASSES) ? __expf(o - mv) : 0.f;
#pragma unroll
    for (int s = 16; s; s >>= 1) ex += __shfl_xor_sync(0xffffffffu, ex, s);
    float res = o - mv - logf(ex);
    if (lane < N_CLASSES) out[(size_t)n * N_CLASSES + lane] = res;
}

// ---------------- launch ----------------
extern "C" void kernel_launch(void* const* d_in, const int* in_sizes, int n_in,
                              void* d_out, int out_size) {
    const float* x   = (const float*)d_in[0];
    const void*  ei  = d_in[1];
    const float* W1  = (const float*)d_in[2];
    const float* as1 = (const float*)d_in[3];
    const float* ad1 = (const float*)d_in[4];
    const float* b1  = (const float*)d_in[5];
    const float* W2  = (const float*)d_in[6];
    const float* as2 = (const float*)d_in[7];
    const float* ad2 = (const float*)d_in[8];
    const float* b2  = (const float*)d_in[9];
    const float* W3  = (const float*)d_in[10];
    const float* as3 = (const float*)d_in[11];
    const float* ad3 = (const float*)d_in[12];
    const float* b3  = (const float*)d_in[13];
    float* out = (float*)d_out;

    float *bufA, *bufB, *asrc, *adst;
    cudaGetSymbolAddress((void**)&bufA, g_bufA);
    cudaGetSymbolAddress((void**)&bufB, g_bufB);
    cudaGetSymbolAddress((void**)&asrc, g_asrc);
    cudaGetSymbolAddress((void**)&adst, g_adst);

    const int EB = (N_EDGES + 255) / 256;        // 3125
    const int WB = (N_NODES * 32 + 255) / 256;   // 6250 (warp per node)
    const int TB = (N_NODES + 127) / 128;        // 391

    // Side stream + events for overlapping the CSR build with GEMM1.
    static cudaStream_t s2 = nullptr;
    static cudaEvent_t e1 = nullptr, e2 = nullptr;
    if (s2 == nullptr) {
        cudaStreamCreateWithFlags(&s2, cudaStreamNonBlocking);
        cudaEventCreateWithFlags(&e1, cudaEventDisableTiming);
        cudaEventCreateWithFlags(&e2, cudaEventDisableTiming);
    }

    // Fork: CSR build on side stream, GEMM1 on main stream (independent work).
    cudaEventRecord(e1, 0);
    cudaStreamWaitEvent(s2, e1, 0);

    k_init<<<SCAN_BLOCKS, 256, 0, s2>>>(ei);
    k_hist<<<EB, 256, 0, s2>>>(ei);
    k_bsum<<<SCAN_BLOCKS, 256, 0, s2>>>();
    k_lscan<<<SCAN_BLOCKS, 256, 0, s2>>>();
    k_scatter<<<EB, 256, 0, s2>>>(ei);
    cudaEventRecord(e2, s2);

    // layer 1 GEMM (+ fused att coefficients) — does not need the CSR
    k_gemm_tc<<<TB, 256>>>(x, W1, bufA, as1, ad1, asrc, adst, N_NODES, F_IN);

    // Join: aggregation needs both GEMM1 output and the CSR
    cudaStreamWaitEvent(0, e2, 0);
    k_aggr<<<WB, 256>>>(bufA, asrc, adst, b1, bufB, nullptr, nullptr, nullptr, 0);

    // layer 2 (aggregation fuses layer-3 feature projection)
    k_gemm_tc<<<TB, 256>>>(bufB, W2, bufA, as2, ad2, asrc, adst, N_NODES, HIDDEN);
    k_aggr<<<WB, 256>>>(bufA, asrc, adst, b2, bufB, W3, as3, ad3, 1);

    // layer 3 aggregation + log_softmax
    k_aggr3<<<WB, 256>>>(b3, out);
}

// round 14
// speedup vs baseline: 1.1501x; 1.1501x over previous
#include <cuda_runtime.h>
#include <math_constants.h>

#define N_NODES   50000
#define N_EDGES   800000
#define F_IN      300
#define HEADS     4
#define PER_HEAD  32
#define HIDDEN    128
#define N_CLASSES 9
#define NEG_SLOPE 0.2f

#define SCAN_BLOCKS 196   // ceil(50000/256)

// ---------------- scratch (static device globals; no allocation) ----------------
__device__ __align__(16) float g_bufA[N_NODES * HIDDEN];
__device__ __align__(16) float g_bufB[N_NODES * HIDDEN];
__device__ __align__(16) float g_feat3[N_NODES * N_CLASSES];
__device__ __align__(16) float g_asrc[N_NODES * HEADS];
__device__ __align__(16) float g_adst[N_NODES * HEADS];
__device__ float g_asrc3[N_NODES];
__device__ float g_adst3[N_NODES];
__device__ int   g_deg[N_NODES];
__device__ int   g_cur[N_NODES];
__device__ int   g_off[N_NODES + 1];
__device__ int   g_csr[N_EDGES];
__device__ int   g_bsum[SCAN_BLOCKS];
__device__ int   g_boff[SCAN_BLOCKS];
__device__ int   g_is64;

// ---------------- init: zero counters + parallel dtype detection ----------------
__global__ void k_init(const void* ei) {
    int i = blockIdx.x * blockDim.x + threadIdx.x;
    if (i < N_NODES) { g_deg[i] = 0; g_cur[i] = 0; }
    if (blockIdx.x == 0) {
        int ok = 1;
        if (threadIdx.x < 64) {
            long long v = ((const long long*)ei)[threadIdx.x];
            ok = (v >= 0 && v < N_NODES) ? 1 : 0;
        }
        int all = __syncthreads_and(ok);
        if (threadIdx.x == 0) g_is64 = all;
    }
}

__device__ __forceinline__ int edge_at(const void* ei, int idx) {
    if (g_is64) return (int)((const long long*)ei)[idx];
    return ((const int*)ei)[idx];
}

// ---------------- CSR construction ----------------
__global__ void k_hist(const void* __restrict__ ei) {
    int e = blockIdx.x * blockDim.x + threadIdx.x;
    if (e < N_EDGES) {
        int d = edge_at(ei, N_EDGES + e);
        atomicAdd(&g_deg[d], 1);
    }
}

__global__ void k_bsum() {
    __shared__ int s[256];
    int tid = threadIdx.x;
    int i = blockIdx.x * 256 + tid;
    s[tid] = (i < N_NODES) ? g_deg[i] : 0;
    __syncthreads();
    for (int st = 128; st; st >>= 1) {
        if (tid < st) s[tid] += s[tid + st];
        __syncthreads();
    }
    if (tid == 0) g_bsum[blockIdx.x] = s[0];
}

__global__ void k_bscan() {
    __shared__ int s[256];
    int tid = threadIdx.x;
    int orig = (tid < SCAN_BLOCKS) ? g_bsum[tid] : 0;
    s[tid] = orig;
    __syncthreads();
    for (int off = 1; off < 256; off <<= 1) {
        int v = (tid >= off) ? s[tid - off] : 0;
        __syncthreads();
        s[tid] += v;
        __syncthreads();
    }
    if (tid < SCAN_BLOCKS) g_boff[tid] = s[tid] - orig;
    if (tid == 0) g_off[N_NODES] = N_EDGES;
}

__global__ void k_lscan() {
    __shared__ int s[256];
    int tid = threadIdx.x;
    int i = blockIdx.x * 256 + tid;
    int v = (i < N_NODES) ? g_deg[i] : 0;
    s[tid] = v;
    __syncthreads();
    for (int off = 1; off < 256; off <<= 1) {
        int t = (tid >= off) ? s[tid - off] : 0;
        __syncthreads();
        s[tid] += t;
        __syncthreads();
    }
    if (i < N_NODES) g_off[i] = (s[tid] - v) + g_boff[blockIdx.x];
}

__global__ void k_scatter(const void* __restrict__ ei) {
    int e = blockIdx.x * blockDim.x + threadIdx.x;
    if (e < N_EDGES) {
        int src = edge_at(ei, e);
        int dst = edge_at(ei, N_EDGES + e);
        int p = g_off[dst] + atomicAdd(&g_cur[dst], 1);
        g_csr[p] = src;
    }
}

// ---------------- TF32 helpers ----------------
__device__ __forceinline__ unsigned f2tf32(float x) {
    unsigned r;
    asm("cvt.rna.tf32.f32 %0, %1;" : "=r"(r) : "f"(x));
    return r;
}
__device__ __forceinline__ void split_tf32(float x, unsigned& hi, unsigned& lo) {
    hi = f2tf32(x);
    lo = f2tf32(x - __uint_as_float(hi));
}
__device__ __forceinline__ void mma_tf32(float* c, const unsigned* a, unsigned b0, unsigned b1) {
    asm volatile(
        "mma.sync.aligned.m16n8k8.row.col.f32.tf32.tf32.f32 "
        "{%0,%1,%2,%3}, {%4,%5,%6,%7}, {%8,%9}, {%0,%1,%2,%3};\n"
        : "+f"(c[0]), "+f"(c[1]), "+f"(c[2]), "+f"(c[3])
        : "r"(a[0]), "r"(a[1]), "r"(a[2]), "r"(a[3]), "r"(b0), "r"(b1));
}

// ---------------- Tensor-core GEMM (double-buffered) + fused attention epilogue ----------------
// C[M,128] = A[M,K] @ B[K,128]; 2-term TF32 (ah*bh + al*bh).
// Block 128x128, BK=16, 8 warps; 2-stage smem pipeline, one sync per K-tile.
#define GSTRIDE 136
__global__ void __launch_bounds__(256, 2) k_gemm_tc(const float* __restrict__ A,
                                                    const float* __restrict__ B,
                                                    float* __restrict__ C,
                                                    const float* __restrict__ as,
                                                    const float* __restrict__ ad,
                                                    float* __restrict__ asrc,
                                                    float* __restrict__ adst,
                                                    int M, int K) {
    __shared__ float As[2][16 * GSTRIDE];
    __shared__ float Bh[2][16 * GSTRIDE];

    int tid = threadIdx.x;
    int wid = tid >> 5, lane = tid & 31;
    int l4 = lane & 3, lg = lane >> 2;
    int wm = (wid >> 1) * 32;
    int wn = (wid & 1) * 64;
    int mbase = blockIdx.x * 128;

    float c[2][8][4];
#pragma unroll
    for (int mt = 0; mt < 2; mt++)
#pragma unroll
        for (int nt = 0; nt < 8; nt++)
#pragma unroll
            for (int e = 0; e < 4; e++) c[mt][nt][e] = 0.f;

    // ---- prologue: stage tile kt=0 into buffer 0 ----
#pragma unroll
    for (int i = 0; i < 2; i++) {
        int a_id = tid + i * 256;
        int row = a_id >> 2;
        int kq = (a_id & 3) * 4;
        int gr = mbase + row, gc = kq;
        float4 av = make_float4(0.f, 0.f, 0.f, 0.f);
        if (gr < M && gc < K)
            av = *(const float4*)(A + (size_t)gr * K + gc);
        As[0][(kq + 0) * GSTRIDE + row] = av.x;
        As[0][(kq + 1) * GSTRIDE + row] = av.y;
        As[0][(kq + 2) * GSTRIDE + row] = av.z;
        As[0][(kq + 3) * GSTRIDE + row] = av.w;
    }
#pragma unroll
    for (int i = 0; i < 2; i++) {
        int b_id = tid + i * 256;
        int krow = b_id >> 5;
        int col4 = (b_id & 31) * 4;
        float4 bv = make_float4(0.f, 0.f, 0.f, 0.f);
        if (krow < K)
            bv = *(const float4*)(B + (size_t)krow * HIDDEN + col4);
        *(float4*)&Bh[0][krow * GSTRIDE + col4] =
            make_float4(__uint_as_float(f2tf32(bv.x)), __uint_as_float(f2tf32(bv.y)),
                        __uint_as_float(f2tf32(bv.z)), __uint_as_float(f2tf32(bv.w)));
    }
    __syncthreads();

    int p = 0;
    for (int kt = 0; kt < K; kt += 16) {
        int ktn = kt + 16;
        bool more = ktn < K;
        float4 av[2], bv[2];
        if (more) {
#pragma unroll
            for (int i = 0; i < 2; i++) {
                int a_id = tid + i * 256;
                int row = a_id >> 2;
                int kq = (a_id & 3) * 4;
                int gr = mbase + row, gc = ktn + kq;
                av[i] = make_float4(0.f, 0.f, 0.f, 0.f);
                if (gr < M && gc < K)
                    av[i] = *(const float4*)(A + (size_t)gr * K + gc);
            }
#pragma unroll
            for (int i = 0; i < 2; i++) {
                int b_id = tid + i * 256;
                int krow = b_id >> 5;
                int col4 = (b_id & 31) * 4;
                int gk = ktn + krow;
                bv[i] = make_float4(0.f, 0.f, 0.f, 0.f);
                if (gk < K)
                    bv[i] = *(const float4*)(B + (size_t)gk * HIDDEN + col4);
            }
        }

        const unsigned* Bh_u = (const unsigned*)Bh[p];
#pragma unroll
        for (int ks = 0; ks < 16; ks += 8) {
            unsigned ah[2][4], al[2][4];
#pragma unroll
            for (int mt = 0; mt < 2; mt++) {
#pragma unroll
                for (int e = 0; e < 4; e++) {
                    int kk = ks + l4 + ((e >> 1) * 4);
                    int mm = wm + mt * 16 + lg + ((e & 1) * 8);
                    float v = As[p][kk * GSTRIDE + mm];
                    split_tf32(v, ah[mt][e], al[mt][e]);
                }
            }
#pragma unroll
            for (int nt = 0; nt < 8; nt++) {
                int nn = wn + nt * 8 + lg;
                unsigned bh0 = Bh_u[(ks + l4) * GSTRIDE + nn];
                unsigned bh1 = Bh_u[(ks + l4 + 4) * GSTRIDE + nn];
#pragma unroll
                for (int mt = 0; mt < 2; mt++) {
                    mma_tf32(c[mt][nt], ah[mt], bh0, bh1);
                    mma_tf32(c[mt][nt], al[mt], bh0, bh1);
                }
            }
        }

        if (more) {
            int q = p ^ 1;
#pragma unroll
            for (int i = 0; i < 2; i++) {
                int a_id = tid + i * 256;
                int row = a_id >> 2;
                int kq = (a_id & 3) * 4;
                As[q][(kq + 0) * GSTRIDE + row] = av[i].x;
                As[q][(kq + 1) * GSTRIDE + row] = av[i].y;
                As[q][(kq + 2) * GSTRIDE + row] = av[i].z;
                As[q][(kq + 3) * GSTRIDE + row] = av[i].w;
            }
#pragma unroll
            for (int i = 0; i < 2; i++) {
                int b_id = tid + i * 256;
                int krow = b_id >> 5;
                int col4 = (b_id & 31) * 4;
                *(float4*)&Bh[q][krow * GSTRIDE + col4] =
                    make_float4(__uint_as_float(f2tf32(bv[i].x)), __uint_as_float(f2tf32(bv[i].y)),
                                __uint_as_float(f2tf32(bv[i].z)), __uint_as_float(f2tf32(bv[i].w)));
            }
            __syncthreads();
            p = q;
        }
    }

    // ---- writeback C ----
#pragma unroll
    for (int mt = 0; mt < 2; mt++) {
        int r0 = mbase + wm + mt * 16 + lg;
#pragma unroll
        for (int nt = 0; nt < 8; nt++) {
            int col = wn + nt * 8 + 2 * l4;
            if (r0 < M)
                *(float2*)(C + (size_t)r0 * HIDDEN + col) =
                    make_float2(c[mt][nt][0], c[mt][nt][1]);
            if (r0 + 8 < M)
                *(float2*)(C + (size_t)(r0 + 8) * HIDDEN + col) =
                    make_float2(c[mt][nt][2], c[mt][nt][3]);
        }
    }

    // ---- fused attention epilogue: this warp owns heads hbase, hbase+1 ----
    int hbase = wn ? 2 : 0;
#pragma unroll
    for (int mt = 0; mt < 2; mt++) {
        float s0 = 0.f, s1 = 0.f, s8_0 = 0.f, s8_1 = 0.f;
        float t0 = 0.f, t1 = 0.f, t8_0 = 0.f, t8_1 = 0.f;
#pragma unroll
        for (int nt = 0; nt < 8; nt++) {
            int cb = wn + nt * 8 + 2 * l4;
            float a0 = as[cb], a1 = as[cb + 1];
            float d0 = ad[cb], d1 = ad[cb + 1];
            float pp = c[mt][nt][0] * a0 + c[mt][nt][1] * a1;
            float p8 = c[mt][nt][2] * a0 + c[mt][nt][3] * a1;
            float q  = c[mt][nt][0] * d0 + c[mt][nt][1] * d1;
            float q8 = c[mt][nt][2] * d0 + c[mt][nt][3] * d1;
            if (nt < 4) { s0 += pp; s8_0 += p8; t0 += q; t8_0 += q8; }
            else        { s1 += pp; s8_1 += p8; t1 += q; t8_1 += q8; }
        }
#pragma unroll
        for (int o = 1; o <= 2; o <<= 1) {
            s0 += __shfl_xor_sync(0xffffffffu, s0, o);
            s1 += __shfl_xor_sync(0xffffffffu, s1, o);
            s8_0 += __shfl_xor_sync(0xffffffffu, s8_0, o);
            s8_1 += __shfl_xor_sync(0xffffffffu, s8_1, o);
            t0 += __shfl_xor_sync(0xffffffffu, t0, o);
            t1 += __shfl_xor_sync(0xffffffffu, t1, o);
            t8_0 += __shfl_xor_sync(0xffffffffu, t8_0, o);
            t8_1 += __shfl_xor_sync(0xffffffffu, t8_1, o);
        }
        int r0 = mbase + wm + mt * 16 + lg;
        if (l4 == 0) {
            if (r0 < M) {
                asrc[r0 * 4 + hbase] = s0;     asrc[r0 * 4 + hbase + 1] = s1;
                adst[r0 * 4 + hbase] = t0;     adst[r0 * 4 + hbase + 1] = t1;
            }
            if (r0 + 8 < M) {
                asrc[(r0 + 8) * 4 + hbase] = s8_0; asrc[(r0 + 8) * 4 + hbase + 1] = s8_1;
                adst[(r0 + 8) * 4 + hbase] = t8_0; adst[(r0 + 8) * 4 + hbase + 1] = t8_1;
            }
        }
    }
}

// ---------------- fused softmax + aggregation (no max pass), warp/dst ----------------
__global__ void __launch_bounds__(256) k_aggr(const float* __restrict__ feat,
                       const float* __restrict__ asrc, const float* __restrict__ adst,
                       const float* __restrict__ bias, float* __restrict__ out) {
    __shared__ float sw[8][32][4];
    __shared__ int   ss[8][32];
    int warp = threadIdx.x >> 5;
    int n = (blockIdx.x * blockDim.x + threadIdx.x) >> 5;
    int lane = threadIdx.x & 31;
    if (n >= N_NODES) return;
    int beg = g_off[n], end = g_off[n + 1];
    int h = lane >> 3;

    float4 ad4 = *(const float4*)(adst + (size_t)n * 4);

    float4 acc = make_float4(0.f, 0.f, 0.f, 0.f);
    float den = 0.f;

    for (int bse = beg; bse < end; bse += 32) {
        int i = bse + lane;
        int s = 0;
        float4 w4 = make_float4(0.f, 0.f, 0.f, 0.f);
        if (i < end) {
            s = g_csr[i];
            float4 a4 = *(const float4*)(asrc + (size_t)s * 4);
            float ex_, ey_, ez_, ew_;
            ex_ = a4.x + ad4.x; ex_ = (ex_ > 0.f) ? ex_ : NEG_SLOPE * ex_;
            ey_ = a4.y + ad4.y; ey_ = (ey_ > 0.f) ? ey_ : NEG_SLOPE * ey_;
            ez_ = a4.z + ad4.z; ez_ = (ez_ > 0.f) ? ez_ : NEG_SLOPE * ez_;
            ew_ = a4.w + ad4.w; ew_ = (ew_ > 0.f) ? ew_ : NEG_SLOPE * ew_;
            w4.x = __expf(fminf(ex_, 60.f));
            w4.y = __expf(fminf(ey_, 60.f));
            w4.z = __expf(fminf(ez_, 60.f));
            w4.w = __expf(fminf(ew_, 60.f));
        }
        ss[warp][lane] = s;
        *(float4*)&sw[warp][lane][0] = w4;
        __syncwarp();

        int cnt = min(32, end - bse);
        int j = 0;
        for (; j + 4 <= cnt; j += 4) {
            int s0 = ss[warp][j],     s1 = ss[warp][j + 1];
            int s2 = ss[warp][j + 2], s3 = ss[warp][j + 3];
            float w0 = sw[warp][j][h],     w1 = sw[warp][j + 1][h];
            float w2 = sw[warp][j + 2][h], w3 = sw[warp][j + 3][h];
            float4 v0 = *(const float4*)(feat + (size_t)s0 * HIDDEN + lane * 4);
            float4 v1 = *(const float4*)(feat + (size_t)s1 * HIDDEN + lane * 4);
            float4 v2 = *(const float4*)(feat + (size_t)s2 * HIDDEN + lane * 4);
            float4 v3 = *(const float4*)(feat + (size_t)s3 * HIDDEN + lane * 4);
            acc.x = fmaf(w0, v0.x, acc.x); acc.y = fmaf(w0, v0.y, acc.y);
            acc.z = fmaf(w0, v0.z, acc.z); acc.w = fmaf(w0, v0.w, acc.w);
            acc.x = fmaf(w1, v1.x, acc.x); acc.y = fmaf(w1, v1.y, acc.y);
            acc.z = fmaf(w1, v1.z, acc.z); acc.w = fmaf(w1, v1.w, acc.w);
            acc.x = fmaf(w2, v2.x, acc.x); acc.y = fmaf(w2, v2.y, acc.y);
            acc.z = fmaf(w2, v2.z, acc.z); acc.w = fmaf(w2, v2.w, acc.w);
            acc.x = fmaf(w3, v3.x, acc.x); acc.y = fmaf(w3, v3.y, acc.y);
            acc.z = fmaf(w3, v3.z, acc.z); acc.w = fmaf(w3, v3.w, acc.w);
            den += (w0 + w1) + (w2 + w3);
        }
        for (; j < cnt; j++) {
            int sj = ss[warp][j];
            float wj = sw[warp][j][h];
            float4 v = *(const float4*)(feat + (size_t)sj * HIDDEN + lane * 4);
            acc.x = fmaf(wj, v.x, acc.x); acc.y = fmaf(wj, v.y, acc.y);
            acc.z = fmaf(wj, v.z, acc.z); acc.w = fmaf(wj, v.w, acc.w);
            den += wj;
        }
        __syncwarp();
    }
    bool has = (end > beg);
    float inv = has ? (1.f / den) : 0.f;
    float4 bv = *(const float4*)(bias + lane * 4);
    float4 o;
    o.x = acc.x * inv + bv.x;
    o.y = acc.y * inv + bv.y;
    o.z = acc.z * inv + bv.z;
    o.w = acc.w * inv + bv.w;
    o.x = (o.x > 0.f) ? o.x : expm1f(o.x);
    o.y = (o.y > 0.f) ? o.y : expm1f(o.y);
    o.z = (o.z > 0.f) ? o.z : expm1f(o.z);
    o.w = (o.w > 0.f) ? o.w : expm1f(o.w);
    *(float4*)(out + (size_t)n * HIDDEN + lane * 4) = o;
}

// ---------------- layer 3 features + attention scalars ----------------
__global__ void k_l3feat(const float* __restrict__ x, const float* __restrict__ W3,
                         const float* __restrict__ as3, const float* __restrict__ ad3) {
    int n = (blockIdx.x * blockDim.x + threadIdx.x) >> 5;
    int lane = threadIdx.x & 31;
    if (n >= N_NODES) return;
    float v[4];
#pragma unroll
    for (int j = 0; j < 4; j++) v[j] = x[(size_t)n * HIDDEN + j * 32 + lane];
    float hc[N_CLASSES];
#pragma unroll
    for (int c = 0; c < N_CLASSES; c++) {
        float p = 0.f;
#pragma unroll
        for (int j = 0; j < 4; j++)
            p = fmaf(v[j], W3[(j * 32 + lane) * N_CLASSES + c], p);
#pragma unroll
        for (int o = 16; o; o >>= 1) p += __shfl_xor_sync(0xffffffffu, p, o);
        hc[c] = p;
    }
    if (lane == 0) {
        float s = 0.f, d = 0.f;
#pragma unroll
        for (int c = 0; c < N_CLASSES; c++) {
            g_feat3[n * N_CLASSES + c] = hc[c];
            s = fmaf(hc[c], as3[c], s);
            d = fmaf(hc[c], ad3[c], d);
        }
        g_asrc3[n] = s;
        g_adst3[n] = d;
    }
}

// ---------------- layer-3 aggregation (no max pass) + ELU + log_softmax ----------------
__global__ void k_aggr3(const float* __restrict__ b3, float* __restrict__ out) {
    int n = (blockIdx.x * blockDim.x + threadIdx.x) >> 5;
    int lane = threadIdx.x & 31;
    if (n >= N_NODES) return;
    int beg = g_off[n], end = g_off[n + 1];
    float adn = g_adst3[n];

    float acc = 0.f, den = 0.f;
    for (int bse = beg; bse < end; bse += 32) {
        int i = bse + lane;
        int s = 0;
        float wg = 0.f;
        if (i < end) {
            s = g_csr[i];
            float e = g_asrc3[s] + adn;
            e = (e > 0.f) ? e : NEG_SLOPE * e;
            wg = __expf(fminf(e, 60.f));
        }
        int cnt = min(32, end - bse);
        int j = 0;
        for (; j + 4 <= cnt; j += 4) {
            int s0 = __shfl_sync(0xffffffffu, s, j);
            int s1 = __shfl_sync(0xffffffffu, s, j + 1);
            int s2 = __shfl_sync(0xffffffffu, s, j + 2);
            int s3 = __shfl_sync(0xffffffffu, s, j + 3);
            float w0 = __shfl_sync(0xffffffffu, wg, j);
            float w1 = __shfl_sync(0xffffffffu, wg, j + 1);
            float w2 = __shfl_sync(0xffffffffu, wg, j + 2);
            float w3 = __shfl_sync(0xffffffffu, wg, j + 3);
            if (lane < N_CLASSES) {
                float f0 = g_feat3[s0 * N_CLASSES + lane];
                float f1 = g_feat3[s1 * N_CLASSES + lane];
                float f2 = g_feat3[s2 * N_CLASSES + lane];
                float f3 = g_feat3[s3 * N_CLASSES + lane];
                acc = fmaf(w0, f0, acc); acc = fmaf(w1, f1, acc);
                acc = fmaf(w2, f2, acc); acc = fmaf(w3, f3, acc);
            }
            den += (w0 + w1) + (w2 + w3);
        }
        for (; j < cnt; j++) {
            int sj = __shfl_sync(0xffffffffu, s, j);
            float wj = __shfl_sync(0xffffffffu, wg, j);
            if (lane < N_CLASSES)
                acc = fmaf(wj, g_feat3[sj * N_CLASSES + lane], acc);
            den += wj;
        }
    }
    float o = (end > beg) ? (acc / den) : 0.f;
    if (lane < N_CLASSES) {
        o += b3[lane];
        o = (o > 0.f) ? o : expm1f(o);
    }
    float mv = (lane < N_CLASSES) ? o : -CUDART_INF_F;
#pragma unroll
    for (int s = 16; s; s >>= 1) mv = fmaxf(mv, __shfl_xor_sync(0xffffffffu, mv, s));
    float ex = (lane < N_CLASSES) ? __expf(o - mv) : 0.f;
#pragma unroll
    for (int s = 16; s; s >>= 1) ex += __shfl_xor_sync(0xffffffffu, ex, s);
    float res = o - mv - logf(ex);
    if (lane < N_CLASSES) out[(size_t)n * N_CLASSES + lane] = res;
}

// ---------------- launch ----------------
extern "C" void kernel_launch(void* const* d_in, const int* in_sizes, int n_in,
                              void* d_out, int out_size) {
    const float* x   = (const float*)d_in[0];
    const void*  ei  = d_in[1];
    const float* W1  = (const float*)d_in[2];
    const float* as1 = (const float*)d_in[3];
    const float* ad1 = (const float*)d_in[4];
    const float* b1  = (const float*)d_in[5];
    const float* W2  = (const float*)d_in[6];
    const float* as2 = (const float*)d_in[7];
    const float* ad2 = (const float*)d_in[8];
    const float* b2  = (const float*)d_in[9];
    const float* W3  = (const float*)d_in[10];
    const float* as3 = (const float*)d_in[11];
    const float* ad3 = (const float*)d_in[12];
    const float* b3  = (const float*)d_in[13];
    float* out = (float*)d_out;

    float *bufA, *bufB, *asrc, *adst;
    cudaGetSymbolAddress((void**)&bufA, g_bufA);
    cudaGetSymbolAddress((void**)&bufB, g_bufB);
    cudaGetSymbolAddress((void**)&asrc, g_asrc);
    cudaGetSymbolAddress((void**)&adst, g_adst);

    const int EB = (N_EDGES + 255) / 256;        // 3125
    const int WB = (N_NODES * 32 + 255) / 256;   // 6250 (warp per node)
    const int TB = (N_NODES + 127) / 128;        // 391

    // Side stream + events for overlapping the CSR build with GEMM1.
    static cudaStream_t s2 = nullptr;
    static cudaEvent_t e1 = nullptr, e2 = nullptr;
    if (s2 == nullptr) {
        cudaStreamCreateWithFlags(&s2, cudaStreamNonBlocking);
        cudaEventCreateWithFlags(&e1, cudaEventDisableTiming);
        cudaEventCreateWithFlags(&e2, cudaEventDisableTiming);
    }

    // Fork: CSR build on side stream, GEMM1 on main stream (independent work).
    cudaEventRecord(e1, 0);
    cudaStreamWaitEvent(s2, e1, 0);

    k_init<<<SCAN_BLOCKS, 256, 0, s2>>>(ei);
    k_hist<<<EB, 256, 0, s2>>>(ei);
    k_bsum<<<SCAN_BLOCKS, 256, 0, s2>>>();
    k_bscan<<<1, 256, 0, s2>>>();
    k_lscan<<<SCAN_BLOCKS, 256, 0, s2>>>();
    k_scatter<<<EB, 256, 0, s2>>>(ei);
    cudaEventRecord(e2, s2);

    // layer 1 GEMM (+ fused att coefficients) — does not need the CSR
    k_gemm_tc<<<TB, 256>>>(x, W1, bufA, as1, ad1, asrc, adst, N_NODES, F_IN);

    // Join: aggregation needs both GEMM1 output and the CSR
    cudaStreamWaitEvent(0, e2, 0);
    k_aggr<<<WB, 256>>>(bufA, asrc, adst, b1, bufB);

    // layer 2
    k_gemm_tc<<<TB, 256>>>(bufB, W2, bufA, as2, ad2, asrc, adst, N_NODES, HIDDEN);
    k_aggr<<<WB, 256>>>(bufA, asrc, adst, b2, bufB);

    // layer 3
    k_l3feat<<<WB, 256>>>(bufB, W3, as3, ad3);
    k_aggr3<<<WB, 256>>>(b3, out);
}

// round 16
// speedup vs baseline: 1.1812x; 1.0271x over previous
#include <cuda_runtime.h>
#include <cuda_fp16.h>
#include <math_constants.h>

#define N_NODES   50000
#define N_EDGES   800000
#define F_IN      300
#define HEADS     4
#define PER_HEAD  32
#define HIDDEN    128
#define N_CLASSES 9
#define NEG_SLOPE 0.2f

#define SCAN_BLOCKS 196   // ceil(50000/256)

// ---------------- scratch (static device globals; no allocation) ----------------
__device__ __align__(16) __half g_featH[N_NODES * HIDDEN];   // GEMM out (fp16, gather src)
__device__ __align__(16) float  g_bufB[N_NODES * HIDDEN];    // activations (fp32)
__device__ __align__(16) float  g_feat3[N_NODES * N_CLASSES];
__device__ __align__(16) float  g_asrc[N_NODES * HEADS];
__device__ __align__(16) float  g_adst[N_NODES * HEADS];
__device__ float g_asrc3[N_NODES];
__device__ float g_adst3[N_NODES];
__device__ int   g_deg[N_NODES];
__device__ int   g_cur[N_NODES];
__device__ int   g_off[N_NODES + 1];
__device__ int   g_csr[N_EDGES];
__device__ int   g_bsum[SCAN_BLOCKS];
__device__ int   g_boff[SCAN_BLOCKS];
__device__ int   g_is64;

// ---------------- init: zero counters + parallel dtype detection ----------------
__global__ void k_init(const void* ei) {
    int i = blockIdx.x * blockDim.x + threadIdx.x;
    if (i < N_NODES) { g_deg[i] = 0; g_cur[i] = 0; }
    if (blockIdx.x == 0) {
        int ok = 1;
        if (threadIdx.x < 64) {
            long long v = ((const long long*)ei)[threadIdx.x];
            ok = (v >= 0 && v < N_NODES) ? 1 : 0;
        }
        int all = __syncthreads_and(ok);
        if (threadIdx.x == 0) g_is64 = all;
    }
}

__device__ __forceinline__ int edge_at(const void* ei, int idx) {
    if (g_is64) return (int)((const long long*)ei)[idx];
    return ((const int*)ei)[idx];
}

// ---------------- CSR construction ----------------
__global__ void k_hist(const void* __restrict__ ei) {
    int e = blockIdx.x * blockDim.x + threadIdx.x;
    if (e < N_EDGES) {
        int d = edge_at(ei, N_EDGES + e);
        atomicAdd(&g_deg[d], 1);
    }
}

__global__ void k_bsum() {
    __shared__ int s[256];
    int tid = threadIdx.x;
    int i = blockIdx.x * 256 + tid;
    s[tid] = (i < N_NODES) ? g_deg[i] : 0;
    __syncthreads();
    for (int st = 128; st; st >>= 1) {
        if (tid < st) s[tid] += s[tid + st];
        __syncthreads();
    }
    if (tid == 0) g_bsum[blockIdx.x] = s[0];
}

__global__ void k_bscan() {
    __shared__ int s[256];
    int tid = threadIdx.x;
    int orig = (tid < SCAN_BLOCKS) ? g_bsum[tid] : 0;
    s[tid] = orig;
    __syncthreads();
    for (int off = 1; off < 256; off <<= 1) {
        int v = (tid >= off) ? s[tid - off] : 0;
        __syncthreads();
        s[tid] += v;
        __syncthreads();
    }
    if (tid < SCAN_BLOCKS) g_boff[tid] = s[tid] - orig;
    if (tid == 0) g_off[N_NODES] = N_EDGES;
}

__global__ void k_lscan() {
    __shared__ int s[256];
    int tid = threadIdx.x;
    int i = blockIdx.x * 256 + tid;
    int v = (i < N_NODES) ? g_deg[i] : 0;
    s[tid] = v;
    __syncthreads();
    for (int off = 1; off < 256; off <<= 1) {
        int t = (tid >= off) ? s[tid - off] : 0;
        __syncthreads();
        s[tid] += t;
        __syncthreads();
    }
    if (i < N_NODES) g_off[i] = (s[tid] - v) + g_boff[blockIdx.x];
}

__global__ void k_scatter(const void* __restrict__ ei) {
    int e = blockIdx.x * blockDim.x + threadIdx.x;
    if (e < N_EDGES) {
        int src = edge_at(ei, e);
        int dst = edge_at(ei, N_EDGES + e);
        int p = g_off[dst] + atomicAdd(&g_cur[dst], 1);
        g_csr[p] = src;
    }
}

// ---------------- TF32 helpers ----------------
__device__ __forceinline__ unsigned f2tf32(float x) {
    unsigned r;
    asm("cvt.rna.tf32.f32 %0, %1;" : "=r"(r) : "f"(x));
    return r;
}
__device__ __forceinline__ void split_tf32(float x, unsigned& hi, unsigned& lo) {
    hi = f2tf32(x);
    lo = f2tf32(x - __uint_as_float(hi));
}
__device__ __forceinline__ void mma_tf32(float* c, const unsigned* a, unsigned b0, unsigned b1) {
    asm volatile(
        "mma.sync.aligned.m16n8k8.row.col.f32.tf32.tf32.f32 "
        "{%0,%1,%2,%3}, {%4,%5,%6,%7}, {%8,%9}, {%0,%1,%2,%3};\n"
        : "+f"(c[0]), "+f"(c[1]), "+f"(c[2]), "+f"(c[3])
        : "r"(a[0]), "r"(a[1]), "r"(a[2]), "r"(a[3]), "r"(b0), "r"(b1));
}

// ---------------- Tensor-core GEMM (double-buffered) + fused attention epilogue ----------------
// C[M,128] (fp16) = A[M,K] @ B[K,128]; 2-term TF32 (ah*bh + al*bh).
// Attention coefficients computed from fp32 accumulators (full precision).
#define GSTRIDE 136
__global__ void __launch_bounds__(256, 2) k_gemm_tc(const float* __restrict__ A,
                                                    const float* __restrict__ B,
                                                    __half* __restrict__ C,
                                                    const float* __restrict__ as,
                                                    const float* __restrict__ ad,
                                                    float* __restrict__ asrc,
                                                    float* __restrict__ adst,
                                                    int M, int K) {
    __shared__ float As[2][16 * GSTRIDE];
    __shared__ float Bh[2][16 * GSTRIDE];

    int tid = threadIdx.x;
    int wid = tid >> 5, lane = tid & 31;
    int l4 = lane & 3, lg = lane >> 2;
    int wm = (wid >> 1) * 32;
    int wn = (wid & 1) * 64;
    int mbase = blockIdx.x * 128;

    float c[2][8][4];
#pragma unroll
    for (int mt = 0; mt < 2; mt++)
#pragma unroll
        for (int nt = 0; nt < 8; nt++)
#pragma unroll
            for (int e = 0; e < 4; e++) c[mt][nt][e] = 0.f;

    // ---- prologue: stage tile kt=0 into buffer 0 ----
#pragma unroll
    for (int i = 0; i < 2; i++) {
        int a_id = tid + i * 256;
        int row = a_id >> 2;
        int kq = (a_id & 3) * 4;
        int gr = mbase + row, gc = kq;
        float4 av = make_float4(0.f, 0.f, 0.f, 0.f);
        if (gr < M && gc < K)
            av = *(const float4*)(A + (size_t)gr * K + gc);
        As[0][(kq + 0) * GSTRIDE + row] = av.x;
        As[0][(kq + 1) * GSTRIDE + row] = av.y;
        As[0][(kq + 2) * GSTRIDE + row] = av.z;
        As[0][(kq + 3) * GSTRIDE + row] = av.w;
    }
#pragma unroll
    for (int i = 0; i < 2; i++) {
        int b_id = tid + i * 256;
        int krow = b_id >> 5;
        int col4 = (b_id & 31) * 4;
        float4 bv = make_float4(0.f, 0.f, 0.f, 0.f);
        if (krow < K)
            bv = *(const float4*)(B + (size_t)krow * HIDDEN + col4);
        *(float4*)&Bh[0][krow * GSTRIDE + col4] =
            make_float4(__uint_as_float(f2tf32(bv.x)), __uint_as_float(f2tf32(bv.y)),
                        __uint_as_float(f2tf32(bv.z)), __uint_as_float(f2tf32(bv.w)));
    }
    __syncthreads();

    int p = 0;
    for (int kt = 0; kt < K; kt += 16) {
        int ktn = kt + 16;
        bool more = ktn < K;
        float4 av[2], bv[2];
        if (more) {
#pragma unroll
            for (int i = 0; i < 2; i++) {
                int a_id = tid + i * 256;
                int row = a_id >> 2;
                int kq = (a_id & 3) * 4;
                int gr = mbase + row, gc = ktn + kq;
                av[i] = make_float4(0.f, 0.f, 0.f, 0.f);
                if (gr < M && gc < K)
                    av[i] = *(const float4*)(A + (size_t)gr * K + gc);
            }
#pragma unroll
            for (int i = 0; i < 2; i++) {
                int b_id = tid + i * 256;
                int krow = b_id >> 5;
                int col4 = (b_id & 31) * 4;
                int gk = ktn + krow;
                bv[i] = make_float4(0.f, 0.f, 0.f, 0.f);
                if (gk < K)
                    bv[i] = *(const float4*)(B + (size_t)gk * HIDDEN + col4);
            }
        }

        const unsigned* Bh_u = (const unsigned*)Bh[p];
#pragma unroll
        for (int ks = 0; ks < 16; ks += 8) {
            unsigned ah[2][4], al[2][4];
#pragma unroll
            for (int mt = 0; mt < 2; mt++) {
#pragma unroll
                for (int e = 0; e < 4; e++) {
                    int kk = ks + l4 + ((e >> 1) * 4);
                    int mm = wm + mt * 16 + lg + ((e & 1) * 8);
                    float v = As[p][kk * GSTRIDE + mm];
                    split_tf32(v, ah[mt][e], al[mt][e]);
                }
            }
#pragma unroll
            for (int nt = 0; nt < 8; nt++) {
                int nn = wn + nt * 8 + lg;
                unsigned bh0 = Bh_u[(ks + l4) * GSTRIDE + nn];
                unsigned bh1 = Bh_u[(ks + l4 + 4) * GSTRIDE + nn];
#pragma unroll
                for (int mt = 0; mt < 2; mt++) {
                    mma_tf32(c[mt][nt], ah[mt], bh0, bh1);
                    mma_tf32(c[mt][nt], al[mt], bh0, bh1);
                }
            }
        }

        if (more) {
            int q = p ^ 1;
#pragma unroll
            for (int i = 0; i < 2; i++) {
                int a_id = tid + i * 256;
                int row = a_id >> 2;
                int kq = (a_id & 3) * 4;
                As[q][(kq + 0) * GSTRIDE + row] = av[i].x;
                As[q][(kq + 1) * GSTRIDE + row] = av[i].y;
                As[q][(kq + 2) * GSTRIDE + row] = av[i].z;
                As[q][(kq + 3) * GSTRIDE + row] = av[i].w;
            }
#pragma unroll
            for (int i = 0; i < 2; i++) {
                int b_id = tid + i * 256;
                int krow = b_id >> 5;
                int col4 = (b_id & 31) * 4;
                *(float4*)&Bh[q][krow * GSTRIDE + col4] =
                    make_float4(__uint_as_float(f2tf32(bv[i].x)), __uint_as_float(f2tf32(bv[i].y)),
                                __uint_as_float(f2tf32(bv[i].z)), __uint_as_float(f2tf32(bv[i].w)));
            }
            __syncthreads();
            p = q;
        }
    }

    // ---- writeback C as fp16 ----
#pragma unroll
    for (int mt = 0; mt < 2; mt++) {
        int r0 = mbase + wm + mt * 16 + lg;
#pragma unroll
        for (int nt = 0; nt < 8; nt++) {
            int col = wn + nt * 8 + 2 * l4;
            if (r0 < M)
                *(__half2*)(C + (size_t)r0 * HIDDEN + col) =
                    __floats2half2_rn(c[mt][nt][0], c[mt][nt][1]);
            if (r0 + 8 < M)
                *(__half2*)(C + (size_t)(r0 + 8) * HIDDEN + col) =
                    __floats2half2_rn(c[mt][nt][2], c[mt][nt][3]);
        }
    }

    // ---- fused attention epilogue (fp32 accumulators): heads hbase, hbase+1 ----
    int hbase = wn ? 2 : 0;
#pragma unroll
    for (int mt = 0; mt < 2; mt++) {
        float s0 = 0.f, s1 = 0.f, s8_0 = 0.f, s8_1 = 0.f;
        float t0 = 0.f, t1 = 0.f, t8_0 = 0.f, t8_1 = 0.f;
#pragma unroll
        for (int nt = 0; nt < 8; nt++) {
            int cb = wn + nt * 8 + 2 * l4;
            float a0 = as[cb], a1 = as[cb + 1];
            float d0 = ad[cb], d1 = ad[cb + 1];
            float pp = c[mt][nt][0] * a0 + c[mt][nt][1] * a1;
            float p8 = c[mt][nt][2] * a0 + c[mt][nt][3] * a1;
            float q  = c[mt][nt][0] * d0 + c[mt][nt][1] * d1;
            float q8 = c[mt][nt][2] * d0 + c[mt][nt][3] * d1;
            if (nt < 4) { s0 += pp; s8_0 += p8; t0 += q; t8_0 += q8; }
            else        { s1 += pp; s8_1 += p8; t1 += q; t8_1 += q8; }
        }
#pragma unroll
        for (int o = 1; o <= 2; o <<= 1) {
            s0 += __shfl_xor_sync(0xffffffffu, s0, o);
            s1 += __shfl_xor_sync(0xffffffffu, s1, o);
            s8_0 += __shfl_xor_sync(0xffffffffu, s8_0, o);
            s8_1 += __shfl_xor_sync(0xffffffffu, s8_1, o);
            t0 += __shfl_xor_sync(0xffffffffu, t0, o);
            t1 += __shfl_xor_sync(0xffffffffu, t1, o);
            t8_0 += __shfl_xor_sync(0xffffffffu, t8_0, o);
            t8_1 += __shfl_xor_sync(0xffffffffu, t8_1, o);
        }
        int r0 = mbase + wm + mt * 16 + lg;
        if (l4 == 0) {
            if (r0 < M) {
                asrc[r0 * 4 + hbase] = s0;     asrc[r0 * 4 + hbase + 1] = s1;
                adst[r0 * 4 + hbase] = t0;     adst[r0 * 4 + hbase + 1] = t1;
            }
            if (r0 + 8 < M) {
                asrc[(r0 + 8) * 4 + hbase] = s8_0; asrc[(r0 + 8) * 4 + hbase + 1] = s8_1;
                adst[(r0 + 8) * 4 + hbase] = t8_0; adst[(r0 + 8) * 4 + hbase + 1] = t8_1;
            }
        }
    }
}

// ---------------- fused softmax + aggregation (fp16 feature gather), warp/dst ----------------
__global__ void __launch_bounds__(256) k_aggr(const __half* __restrict__ feat,
                       const float* __restrict__ asrc, const float* __restrict__ adst,
                       const float* __restrict__ bias, float* __restrict__ out) {
    __shared__ float sw[8][32][4];
    __shared__ int   ss[8][32];
    int warp = threadIdx.x >> 5;
    int n = (blockIdx.x * blockDim.x + threadIdx.x) >> 5;
    int lane = threadIdx.x & 31;
    if (n >= N_NODES) return;
    int beg = g_off[n], end = g_off[n + 1];
    int h = lane >> 3;

    float4 ad4 = *(const float4*)(adst + (size_t)n * 4);

    float4 acc = make_float4(0.f, 0.f, 0.f, 0.f);
    float den = 0.f;

    for (int bse = beg; bse < end; bse += 32) {
        int i = bse + lane;
        int s = 0;
        float4 w4 = make_float4(0.f, 0.f, 0.f, 0.f);
        if (i < end) {
            s = g_csr[i];
            float4 a4 = *(const float4*)(asrc + (size_t)s * 4);
            float ex_, ey_, ez_, ew_;
            ex_ = a4.x + ad4.x; ex_ = (ex_ > 0.f) ? ex_ : NEG_SLOPE * ex_;
            ey_ = a4.y + ad4.y; ey_ = (ey_ > 0.f) ? ey_ : NEG_SLOPE * ey_;
            ez_ = a4.z + ad4.z; ez_ = (ez_ > 0.f) ? ez_ : NEG_SLOPE * ez_;
            ew_ = a4.w + ad4.w; ew_ = (ew_ > 0.f) ? ew_ : NEG_SLOPE * ew_;
            w4.x = __expf(fminf(ex_, 60.f));
            w4.y = __expf(fminf(ey_, 60.f));
            w4.z = __expf(fminf(ez_, 60.f));
            w4.w = __expf(fminf(ew_, 60.f));
        }
        ss[warp][lane] = s;
        *(float4*)&sw[warp][lane][0] = w4;
        __syncwarp();

        int cnt = min(32, end - bse);
        int j = 0;
        for (; j + 4 <= cnt; j += 4) {
            int s0 = ss[warp][j],     s1 = ss[warp][j + 1];
            int s2 = ss[warp][j + 2], s3 = ss[warp][j + 3];
            float w0 = sw[warp][j][h],     w1 = sw[warp][j + 1][h];
            float w2 = sw[warp][j + 2][h], w3 = sw[warp][j + 3][h];
            uint2 r0 = *(const uint2*)(feat + (size_t)s0 * HIDDEN + lane * 4);
            uint2 r1 = *(const uint2*)(feat + (size_t)s1 * HIDDEN + lane * 4);
            uint2 r2 = *(const uint2*)(feat + (size_t)s2 * HIDDEN + lane * 4);
            uint2 r3 = *(const uint2*)(feat + (size_t)s3 * HIDDEN + lane * 4);
            float2 a0 = __half22float2(*(__half2*)&r0.x), b0 = __half22float2(*(__half2*)&r0.y);
            float2 a1 = __half22float2(*(__half2*)&r1.x), b1 = __half22float2(*(__half2*)&r1.y);
            float2 a2 = __half22float2(*(__half2*)&r2.x), b2 = __half22float2(*(__half2*)&r2.y);
            float2 a3 = __half22float2(*(__half2*)&r3.x), b3 = __half22float2(*(__half2*)&r3.y);
            acc.x = fmaf(w0, a0.x, acc.x); acc.y = fmaf(w0, a0.y, acc.y);
            acc.z = fmaf(w0, b0.x, acc.z); acc.w = fmaf(w0, b0.y, acc.w);
            acc.x = fmaf(w1, a1.x, acc.x); acc.y = fmaf(w1, a1.y, acc.y);
            acc.z = fmaf(w1, b1.x, acc.z); acc.w = fmaf(w1, b1.y, acc.w);
            acc.x = fmaf(w2, a2.x, acc.x); acc.y = fmaf(w2, a2.y, acc.y);
            acc.z = fmaf(w2, b2.x, acc.z); acc.w = fmaf(w2, b2.y, acc.w);
            acc.x = fmaf(w3, a3.x, acc.x); acc.y = fmaf(w3, a3.y, acc.y);
            acc.z = fmaf(w3, b3.x, acc.z); acc.w = fmaf(w3, b3.y, acc.w);
            den += (w0 + w1) + (w2 + w3);
        }
        for (; j < cnt; j++) {
            int sj = ss[warp][j];
            float wj = sw[warp][j][h];
            uint2 r = *(const uint2*)(feat + (size_t)sj * HIDDEN + lane * 4);
            float2 a = __half22float2(*(__half2*)&r.x), b = __half22float2(*(__half2*)&r.y);
            acc.x = fmaf(wj, a.x, acc.x); acc.y = fmaf(wj, a.y, acc.y);
            acc.z = fmaf(wj, b.x, acc.z); acc.w = fmaf(wj, b.y, acc.w);
            den += wj;
        }
        __syncwarp();
    }
    bool has = (end > beg);
    float inv = has ? (1.f / den) : 0.f;
    float4 bv = *(const float4*)(bias + lane * 4);
    float4 o;
    o.x = acc.x * inv + bv.x;
    o.y = acc.y * inv + bv.y;
    o.z = acc.z * inv + bv.z;
    o.w = acc.w * inv + bv.w;
    o.x = (o.x > 0.f) ? o.x : expm1f(o.x);
    o.y = (o.y > 0.f) ? o.y : expm1f(o.y);
    o.z = (o.z > 0.f) ? o.z : expm1f(o.z);
    o.w = (o.w > 0.f) ? o.w : expm1f(o.w);
    *(float4*)(out + (size_t)n * HIDDEN + lane * 4) = o;
}

// ---------------- layer 3 features + attention scalars ----------------
__global__ void k_l3feat(const float* __restrict__ x, const float* __restrict__ W3,
                         const float* __restrict__ as3, const float* __restrict__ ad3) {
    int n = (blockIdx.x * blockDim.x + threadIdx.x) >> 5;
    int lane = threadIdx.x & 31;
    if (n >= N_NODES) return;
    float v[4];
#pragma unroll
    for (int j = 0; j < 4; j++) v[j] = x[(size_t)n * HIDDEN + j * 32 + lane];
    float hc[N_CLASSES];
#pragma unroll
    for (int c = 0; c < N_CLASSES; c++) {
        float p = 0.f;
#pragma unroll
        for (int j = 0; j < 4; j++)
            p = fmaf(v[j], W3[(j * 32 + lane) * N_CLASSES + c], p);
#pragma unroll
        for (int o = 16; o; o >>= 1) p += __shfl_xor_sync(0xffffffffu, p, o);
        hc[c] = p;
    }
    if (lane == 0) {
        float s = 0.f, d = 0.f;
#pragma unroll
        for (int c = 0; c < N_CLASSES; c++) {
            g_feat3[n * N_CLASSES + c] = hc[c];
            s = fmaf(hc[c], as3[c], s);
            d = fmaf(hc[c], ad3[c], d);
        }
        g_asrc3[n] = s;
        g_adst3[n] = d;
    }
}

// ---------------- layer-3 aggregation (no max pass) + ELU + log_softmax ----------------
__global__ void k_aggr3(const float* __restrict__ b3, float* __restrict__ out) {
    int n = (blockIdx.x * blockDim.x + threadIdx.x) >> 5;
    int lane = threadIdx.x & 31;
    if (n >= N_NODES) return;
    int beg = g_off[n], end = g_off[n + 1];
    float adn = g_adst3[n];

    float acc = 0.f, den = 0.f;
    for (int bse = beg; bse < end; bse += 32) {
        int i = bse + lane;
        int s = 0;
        float wg = 0.f;
        if (i < end) {
            s = g_csr[i];
            float e = g_asrc3[s] + adn;
            e = (e > 0.f) ? e : NEG_SLOPE * e;
            wg = __expf(fminf(e, 60.f));
        }
        int cnt = min(32, end - bse);
        int j = 0;
        for (; j + 4 <= cnt; j += 4) {
            int s0 = __shfl_sync(0xffffffffu, s, j);
            int s1 = __shfl_sync(0xffffffffu, s, j + 1);
            int s2 = __shfl_sync(0xffffffffu, s, j + 2);
            int s3 = __shfl_sync(0xffffffffu, s, j + 3);
            float w0 = __shfl_sync(0xffffffffu, wg, j);
            float w1 = __shfl_sync(0xffffffffu, wg, j + 1);
            float w2 = __shfl_sync(0xffffffffu, wg, j + 2);
            float w3 = __shfl_sync(0xffffffffu, wg, j + 3);
            if (lane < N_CLASSES) {
                float f0 = g_feat3[s0 * N_CLASSES + lane];
                float f1 = g_feat3[s1 * N_CLASSES + lane];
                float f2 = g_feat3[s2 * N_CLASSES + lane];
                float f3 = g_feat3[s3 * N_CLASSES + lane];
                acc = fmaf(w0, f0, acc); acc = fmaf(w1, f1, acc);
                acc = fmaf(w2, f2, acc); acc = fmaf(w3, f3, acc);
            }
            den += (w0 + w1) + (w2 + w3);
        }
        for (; j < cnt; j++) {
            int sj = __shfl_sync(0xffffffffu, s, j);
            float wj = __shfl_sync(0xffffffffu, wg, j);
            if (lane < N_CLASSES)
                acc = fmaf(wj, g_feat3[sj * N_CLASSES + lane], acc);
            den += wj;
        }
    }
    float o = (end > beg) ? (acc / den) : 0.f;
    if (lane < N_CLASSES) {
        o += b3[lane];
        o = (o > 0.f) ? o : expm1f(o);
    }
    float mv = (lane < N_CLASSES) ? o : -CUDART_INF_F;
#pragma unroll
    for (int s = 16; s; s >>= 1) mv = fmaxf(mv, __shfl_xor_sync(0xffffffffu, mv, s));
    float ex = (lane < N_CLASSES) ? __expf(o - mv) : 0.f;
#pragma unroll
    for (int s = 16; s; s >>= 1) ex += __shfl_xor_sync(0xffffffffu, ex, s);
    float res = o - mv - logf(ex);
    if (lane < N_CLASSES) out[(size_t)n * N_CLASSES + lane] = res;
}

// ---------------- launch ----------------
extern "C" void kernel_launch(void* const* d_in, const int* in_sizes, int n_in,
                              void* d_out, int out_size) {
    const float* x   = (const float*)d_in[0];
    const void*  ei  = d_in[1];
    const float* W1  = (const float*)d_in[2];
    const float* as1 = (const float*)d_in[3];
    const float* ad1 = (const float*)d_in[4];
    const float* b1  = (const float*)d_in[5];
    const float* W2  = (const float*)d_in[6];
    const float* as2 = (const float*)d_in[7];
    const float* ad2 = (const float*)d_in[8];
    const float* b2  = (const float*)d_in[9];
    const float* W3  = (const float*)d_in[10];
    const float* as3 = (const float*)d_in[11];
    const float* ad3 = (const float*)d_in[12];
    const float* b3  = (const float*)d_in[13];
    float* out = (float*)d_out;

    __half* featH;
    float *bufB, *asrc, *adst;
    cudaGetSymbolAddress((void**)&featH, g_featH);
    cudaGetSymbolAddress((void**)&bufB, g_bufB);
    cudaGetSymbolAddress((void**)&asrc, g_asrc);
    cudaGetSymbolAddress((void**)&adst, g_adst);

    const int EB = (N_EDGES + 255) / 256;        // 3125
    const int WB = (N_NODES * 32 + 255) / 256;   // 6250 (warp per node)
    const int TB = (N_NODES + 127) / 128;        // 391

    // Side stream + events for overlapping the CSR build with GEMM1.
    static cudaStream_t s2 = nullptr;
    static cudaEvent_t e1 = nullptr, e2 = nullptr;
    if (s2 == nullptr) {
        cudaStreamCreateWithFlags(&s2, cudaStreamNonBlocking);
        cudaEventCreateWithFlags(&e1, cudaEventDisableTiming);
        cudaEventCreateWithFlags(&e2, cudaEventDisableTiming);
    }

    // Fork: CSR build on side stream, GEMM1 on main stream (independent work).
    cudaEventRecord(e1, 0);
    cudaStreamWaitEvent(s2, e1, 0);

    k_init<<<SCAN_BLOCKS, 256, 0, s2>>>(ei);
    k_hist<<<EB, 256, 0, s2>>>(ei);
    k_bsum<<<SCAN_BLOCKS, 256, 0, s2>>>();
    k_bscan<<<1, 256, 0, s2>>>();
    k_lscan<<<SCAN_BLOCKS, 256, 0, s2>>>();
    k_scatter<<<EB, 256, 0, s2>>>(ei);
    cudaEventRecord(e2, s2);

    // layer 1 GEMM (+ fused att coefficients) — does not need the CSR
    k_gemm_tc<<<TB, 256>>>(x, W1, featH, as1, ad1, asrc, adst, N_NODES, F_IN);

    // Join: aggregation needs both GEMM1 output and the CSR
    cudaStreamWaitEvent(0, e2, 0);
    k_aggr<<<WB, 256>>>(featH, asrc, adst, b1, bufB);

    // layer 2
    k_gemm_tc<<<TB, 256>>>(bufB, W2, featH, as2, ad2, asrc, adst, N_NODES, HIDDEN);
    k_aggr<<<WB, 256>>>(featH, asrc, adst, b2, bufB);

    // layer 3
    k_l3feat<<<WB, 256>>>(bufB, W3, as3, ad3);
    k_aggr3<<<WB, 256>>>(b3, out);
}